// round 16
// baseline (speedup 1.0000x reference)
#include <cuda_runtime.h>
#include <cuda_fp16.h>
#include <math.h>
#include <stdint.h>

#define BATCH 2
#define SEQ   2048
#define DMODEL 2048
#define NHEADS 16
#define HDIM  128
#define INNER 2048   // NHEADS*HDIM
#define MROWS 4096   // BATCH*SEQ

// Scratch (device globals — allocation-free per harness rules)
__device__ __half g_xh[(size_t)MROWS * DMODEL];   // x hi fp16
__device__ __half g_xl[(size_t)MROWS * DMODEL];   // x lo fp16
__device__ __half g_wq[(size_t)INNER * DMODEL];
__device__ __half g_wk[(size_t)INNER * DMODEL];
__device__ __half g_wv[(size_t)INNER * DMODEL];
__device__ __half g_wo[(size_t)DMODEL * INNER];
__device__ __half g_qh[(size_t)MROWS * INNER];    // normed+roped+scaled Q
__device__ __half g_kh[(size_t)MROWS * INNER];    // normed+roped K
__device__ __half g_vh[(size_t)MROWS * INNER];    // V
__device__ __half g_oh[(size_t)MROWS * INNER];    // attn out hi
__device__ __half g_ol[(size_t)MROWS * INNER];    // attn out lo

// ===========================================================================
// helpers (sm_80-era features only — nothing 'a'-gated)
// ===========================================================================
__device__ __forceinline__ uint32_t smem_u32(const void* p) {
    uint32_t a;
    asm("{ .reg .u64 t; cvta.to.shared.u64 t, %1; cvt.u32.u64 %0, t; }"
        : "=r"(a) : "l"(p));
    return a;
}

__device__ __forceinline__ void mma_f16(float c[4], const uint32_t a[4],
                                        uint32_t b0, uint32_t b1) {
    asm volatile(
        "mma.sync.aligned.m16n8k16.row.col.f32.f16.f16.f32 "
        "{%0,%1,%2,%3}, {%4,%5,%6,%7}, {%8,%9}, {%0,%1,%2,%3};"
        : "+f"(c[0]), "+f"(c[1]), "+f"(c[2]), "+f"(c[3])
        : "r"(a[0]), "r"(a[1]), "r"(a[2]), "r"(a[3]), "r"(b0), "r"(b1));
}

__device__ __forceinline__ void ldmx4(uint32_t r[4], uint32_t addr) {
    asm volatile("ldmatrix.sync.aligned.m8n8.x4.shared.b16 {%0,%1,%2,%3}, [%4];"
                 : "=r"(r[0]), "=r"(r[1]), "=r"(r[2]), "=r"(r[3]) : "r"(addr));
}

__device__ __forceinline__ void ldmx4t(uint32_t r[4], uint32_t addr) {
    asm volatile("ldmatrix.sync.aligned.m8n8.x4.trans.shared.b16 {%0,%1,%2,%3}, [%4];"
                 : "=r"(r[0]), "=r"(r[1]), "=r"(r[2]), "=r"(r[3]) : "r"(addr));
}

__device__ __forceinline__ void cpa16(uint32_t s, const void* g) {
    asm volatile("cp.async.cg.shared.global [%0], [%1], 16;"
                 :: "r"(s), "l"(g) : "memory");
}
#define CP_COMMIT() asm volatile("cp.async.commit_group;" ::: "memory")
#define CP_WAIT1()  asm volatile("cp.async.wait_group 1;" ::: "memory")

__device__ __forceinline__ void split4(float4 v, __half2& h01, __half2& h23,
                                       __half2& l01, __half2& l23) {
    __half hx = __float2half_rn(v.x), hy = __float2half_rn(v.y);
    __half hz = __float2half_rn(v.z), hw = __float2half_rn(v.w);
    __half lx = __float2half_rn(v.x - __half2float(hx));
    __half ly = __float2half_rn(v.y - __half2float(hy));
    __half lz = __float2half_rn(v.z - __half2float(hz));
    __half lw = __float2half_rn(v.w - __half2float(hw));
    h01 = __halves2half2(hx, hy); h23 = __halves2half2(hz, hw);
    l01 = __halves2half2(lx, ly); l23 = __halves2half2(lz, lw);
}

// ===========================================================================
// Conversion kernels (run once; results reused across GEMMs)
// ===========================================================================
__global__ __launch_bounds__(256)
void conv_split_x(const float* __restrict__ in, __half* __restrict__ hi,
                  __half* __restrict__ lo)
{
    size_t i = ((size_t)blockIdx.x * 256 + threadIdx.x) * 4;
    float4 v = *(const float4*)(in + i);
    __half2 h01, h23, l01, l23;
    split4(v, h01, h23, l01, l23);
    *(__half2*)(hi + i)     = h01;
    *(__half2*)(hi + i + 2) = h23;
    *(__half2*)(lo + i)     = l01;
    *(__half2*)(lo + i + 2) = l23;
}

__global__ __launch_bounds__(256)
void conv_w4(const float* __restrict__ w0, const float* __restrict__ w1,
             const float* __restrict__ w2, const float* __restrict__ w3,
             __half* __restrict__ o0, __half* __restrict__ o1,
             __half* __restrict__ o2, __half* __restrict__ o3)
{
    int z = blockIdx.y;
    const float* src = (z == 0) ? w0 : (z == 1) ? w1 : (z == 2) ? w2 : w3;
    __half* dst      = (z == 0) ? o0 : (z == 1) ? o1 : (z == 2) ? o2 : o3;
    size_t i = ((size_t)blockIdx.x * 256 + threadIdx.x) * 4;
    float4 v = *(const float4*)(src + i);
    *(__half2*)(dst + i)     = __floats2half2_rn(v.x, v.y);
    *(__half2*)(dst + i + 2) = __floats2half2_rn(v.z, v.w);
}

// ===========================================================================
// GEMM: C[M,N] = (Ah+Al)[M,K] @ Bh[N,K]^T, all fp16 inputs in gmem.
// CTA tile 128x128, BK=32, 256 threads (warps 2Mx4N, 64x32),
// 3-stage cp.async pipeline, ldmatrix fragment loads. (UNCHANGED from R13.)
// ===========================================================================
#define BM 128
#define BN 128
#define BK 32
#define LDH 40                              // halves per row (32 + 8 pad), 80 B
#define TILE_H (BM * LDH)                   // 5120 halves per tile
#define STG_H  (3 * TILE_H)                 // Ah, Al, Bh per stage
#define GEMM_SMEM (3 * STG_H * 2)           // 92160 bytes

template<int MODE>
__global__ __launch_bounds__(256, 2)
void gemm_tc(const __half* __restrict__ Ah, const __half* __restrict__ Al,
             const __half* __restrict__ Bh, void* __restrict__ Cout,
             int M, int N, int K,
             const float* __restrict__ w, const float* __restrict__ freqs)
{
    extern __shared__ __align__(16) __half smh[];

    const int tid  = threadIdx.x;
    const int lane = tid & 31;
    const int wid  = tid >> 5;
    const int wm   = (wid & 1) * 64;
    const int wn   = (wid >> 1) * 32;
    const int g    = lane >> 2;
    const int tg   = lane & 3;

    const int rowBase = blockIdx.y * BM;
    const int colBase = blockIdx.x * BN;

    const int cr = tid >> 2;             // 0..63
    const int c16 = tid & 3;             // chunk in 64B row
    const int gofs = c16 * 8;            // halves

    const uint32_t ub   = smem_u32(smh);
    const uint32_t aoff = (uint32_t)((wm + (lane & 15)) * (LDH * 2) + (lane >> 4) * 16);
    const uint32_t boff = (uint32_t)((wn + ((lane >> 4) << 3) + (lane & 7)) * (LDH * 2)
                                     + ((lane >> 3) & 1) * 16);

    float acc[4][4][4];
#pragma unroll
    for (int mi = 0; mi < 4; ++mi)
#pragma unroll
        for (int ni = 0; ni < 4; ++ni)
#pragma unroll
            for (int r = 0; r < 4; ++r) acc[mi][ni][r] = 0.0f;

    const int nkt = K / BK;

    auto issue = [&](int kt, int st) {
        const int k0 = kt * BK;
        uint32_t sb = ub + (uint32_t)st * (STG_H * 2);
        const __half* a0 = Ah + (size_t)(rowBase + cr) * K + k0 + gofs;
        const __half* a1 = Ah + (size_t)(rowBase + 64 + cr) * K + k0 + gofs;
        cpa16(sb + cr * 80 + c16 * 16, a0);
        cpa16(sb + (64 + cr) * 80 + c16 * 16, a1);
        const __half* l0 = Al + (size_t)(rowBase + cr) * K + k0 + gofs;
        const __half* l1 = Al + (size_t)(rowBase + 64 + cr) * K + k0 + gofs;
        cpa16(sb + TILE_H * 2 + cr * 80 + c16 * 16, l0);
        cpa16(sb + TILE_H * 2 + (64 + cr) * 80 + c16 * 16, l1);
        const __half* b0 = Bh + (size_t)(colBase + cr) * K + k0 + gofs;
        const __half* b1 = Bh + (size_t)(colBase + 64 + cr) * K + k0 + gofs;
        cpa16(sb + 2 * TILE_H * 2 + cr * 80 + c16 * 16, b0);
        cpa16(sb + 2 * TILE_H * 2 + (64 + cr) * 80 + c16 * 16, b1);
    };

    issue(0, 0); CP_COMMIT();
    issue(1, 1); CP_COMMIT();

    int rd = 0;
    for (int kt = 0; kt < nkt; ++kt) {
        CP_WAIT1();
        __syncthreads();
        {
            int ws = rd + 2; if (ws >= 3) ws -= 3;
            if (kt + 2 < nkt) issue(kt + 2, ws);
            CP_COMMIT();
        }

        const uint32_t sb = ub + (uint32_t)rd * (STG_H * 2);
        const uint32_t bAh = sb + aoff;
        const uint32_t bAl = sb + TILE_H * 2 + aoff;
        const uint32_t bBh = sb + 2 * TILE_H * 2 + boff;

#pragma unroll
        for (int ks = 0; ks < 2; ++ks) {
            uint32_t ah[4][4], al[4][4], bh[2][4];
#pragma unroll
            for (int mi = 0; mi < 4; ++mi)
                ldmx4(ah[mi], bAh + mi * (16 * LDH * 2) + ks * 32);
#pragma unroll
            for (int mi = 0; mi < 4; ++mi)
                ldmx4(al[mi], bAl + mi * (16 * LDH * 2) + ks * 32);
            ldmx4(bh[0], bBh + ks * 32);
            ldmx4(bh[1], bBh + 16 * LDH * 2 + ks * 32);
#pragma unroll
            for (int mi = 0; mi < 4; ++mi)
#pragma unroll
                for (int ni = 0; ni < 4; ++ni) {
                    uint32_t b0 = bh[ni >> 1][(ni & 1) * 2];
                    uint32_t b1 = bh[ni >> 1][(ni & 1) * 2 + 1];
                    mma_f16(acc[mi][ni], ah[mi], b0, b1);
                    mma_f16(acc[mi][ni], al[mi], b0, b1);
                }
        }
        rd = (rd + 1 == 3) ? 0 : rd + 1;
    }
    __syncthreads();

    // ---------------- Epilogue ----------------
    if (MODE == 0) {
        float* C = (float*)Cout;
#pragma unroll
        for (int mi = 0; mi < 4; ++mi) {
            const int r0 = rowBase + wm + mi * 16 + g;
#pragma unroll
            for (int ni = 0; ni < 4; ++ni) {
                const int c0 = colBase + wn + ni * 8 + tg * 2;
                *(float2*)(C + (size_t)r0 * N + c0) =
                    make_float2(acc[mi][ni][0], acc[mi][ni][1]);
                *(float2*)(C + (size_t)(r0 + 8) * N + c0) =
                    make_float2(acc[mi][ni][2], acc[mi][ni][3]);
            }
        }
    } else if (MODE == 1) {
        __half* C = (__half*)Cout;
#pragma unroll
        for (int mi = 0; mi < 4; ++mi) {
            const int r0 = rowBase + wm + mi * 16 + g;
#pragma unroll
            for (int ni = 0; ni < 4; ++ni) {
                const int c0 = colBase + wn + ni * 8 + tg * 2;
                *(__half2*)(C + (size_t)r0 * N + c0) =
                    __floats2half2_rn(acc[mi][ni][0], acc[mi][ni][1]);
                *(__half2*)(C + (size_t)(r0 + 8) * N + c0) =
                    __floats2half2_rn(acc[mi][ni][2], acc[mi][ni][3]);
            }
        }
    } else {
        float* red = (float*)smh;          // [128][4]
        float* stg = red + 512;            // [128][64]

#pragma unroll
        for (int mi = 0; mi < 4; ++mi) {
            float s0 = 0.0f, s1 = 0.0f;
#pragma unroll
            for (int ni = 0; ni < 4; ++ni) {
                s0 += acc[mi][ni][0] * acc[mi][ni][0] + acc[mi][ni][1] * acc[mi][ni][1];
                s1 += acc[mi][ni][2] * acc[mi][ni][2] + acc[mi][ni][3] * acc[mi][ni][3];
            }
            s0 += __shfl_xor_sync(0xffffffffu, s0, 1);
            s0 += __shfl_xor_sync(0xffffffffu, s0, 2);
            s1 += __shfl_xor_sync(0xffffffffu, s1, 1);
            s1 += __shfl_xor_sync(0xffffffffu, s1, 2);
            if (tg == 0) {
                red[(wm + mi * 16 + g) * 4 + (wn >> 5)]     = s0;
                red[(wm + mi * 16 + g + 8) * 4 + (wn >> 5)] = s1;
            }
        }
        __syncthreads();

        const float xsc = (MODE == 3) ? 0.08838834764831845f : 1.0f;
        float wc[4][2];
#pragma unroll
        for (int ni = 0; ni < 4; ++ni) {
            int c = wn + ni * 8 + tg * 2;
            wc[ni][0] = w[c]; wc[ni][1] = w[c + 1];
        }
#pragma unroll
        for (int mi = 0; mi < 4; ++mi) {
            int r = wm + mi * 16 + g;
            float4 p0 = *(float4*)&red[r * 4];
            float4 p1 = *(float4*)&red[(r + 8) * 4];
            float rms0 = rsqrtf((p0.x + p0.y + p0.z + p0.w) * (1.0f / 128.0f) + 1e-6f) * xsc;
            float rms1 = rsqrtf((p1.x + p1.y + p1.z + p1.w) * (1.0f / 128.0f) + 1e-6f) * xsc;
#pragma unroll
            for (int ni = 0; ni < 4; ++ni) {
                acc[mi][ni][0] *= rms0 * wc[ni][0];
                acc[mi][ni][1] *= rms0 * wc[ni][1];
                acc[mi][ni][2] *= rms1 * wc[ni][0];
                acc[mi][ni][3] *= rms1 * wc[ni][1];
            }
        }

        if (wn >= 64) {
#pragma unroll
            for (int mi = 0; mi < 4; ++mi) {
                int r = wm + mi * 16 + g;
#pragma unroll
                for (int ni = 0; ni < 4; ++ni) {
                    int cc = wn - 64 + ni * 8 + tg * 2;
                    *(float2*)&stg[r * 64 + cc] =
                        make_float2(acc[mi][ni][0], acc[mi][ni][1]);
                    *(float2*)&stg[(r + 8) * 64 + cc] =
                        make_float2(acc[mi][ni][2], acc[mi][ni][3]);
                }
            }
        }
        __syncthreads();

        if (wn < 64) {
            __half* C = (__half*)Cout;
#pragma unroll
            for (int mi = 0; mi < 4; ++mi) {
#pragma unroll
                for (int h2 = 0; h2 < 2; ++h2) {
                    int r = wm + mi * 16 + g + 8 * h2;
                    int rowg = rowBase + r;
                    int s = rowg & (SEQ - 1);
#pragma unroll
                    for (int ni = 0; ni < 4; ++ni) {
                        int j = wn + ni * 8 + tg * 2;
                        float nj0 = acc[mi][ni][2 * h2];
                        float nj1 = acc[mi][ni][2 * h2 + 1];
                        float2 mm = *(float2*)&stg[r * 64 + j];
                        float4 f0 = *(const float4*)(freqs + (size_t)s * 256 + j * 4);
                        float4 f1 = *(const float4*)(freqs + (size_t)s * 256 + (j + 1) * 4);
                        float oj0    = f0.x * nj0 + f0.y * mm.x;
                        float oj64_0 = f0.z * nj0 + f0.w * mm.x;
                        float oj1    = f1.x * nj1 + f1.y * mm.y;
                        float oj64_1 = f1.z * nj1 + f1.w * mm.y;
                        __half* cp = C + (size_t)rowg * N + colBase + j;
                        *(__half2*)cp        = __floats2half2_rn(oj0, oj1);
                        *(__half2*)(cp + 64) = __floats2half2_rn(oj64_0, oj64_1);
                    }
                }
            }
        }
    }
}

// ===========================================================================
// fp16 tensor flash attention. 256 threads (8 warps), BQ=128, BK=64, HDIM=128.
// 3-stage cp.async K/V pipeline. Q fragments preloaded to registers;
// P stays in registers (S accum layout == PV A-fragment layout).
// ===========================================================================
#define AQ_LD 136                            // 272 B rows, ldmatrix conflict-free
#define KO 17408                             // Q = 128*136 halves
#define VO (KO + 3 * 64 * AQ_LD)             // 43520
#define ATTN_SMEM ((VO + 3 * 64 * AQ_LD) * 2)   // 139264 bytes
#define KVSTG (64 * AQ_LD * 2)               // 17408 bytes per stage

__global__ __launch_bounds__(256)
void attn_kernel(const __half* __restrict__ q, const __half* __restrict__ k,
                 const __half* __restrict__ v,
                 __half* __restrict__ oh, __half* __restrict__ ol)
{
    extern __shared__ __align__(16) __half sh[];
    __half* Qh = sh;

    const int tid  = threadIdx.x;
    const int lane = tid & 31;
    const int wid  = tid >> 5;
    const int g    = lane >> 2;
    const int tg   = lane & 3;
    const int m0   = wid * 16;

    const int qt = blockIdx.x, h = blockIdx.y, b = blockIdx.z;
    const __half* qb  = q + ((size_t)(b * SEQ + qt * 128)) * INNER + h * HDIM;
    const __half* kb0 = k + (size_t)b * SEQ * INNER + h * HDIM;
    const __half* vb0 = v + (size_t)b * SEQ * INNER + h * HDIM;

    const uint32_t ubs = smem_u32(sh);
    const int rr0 = tid >> 4;                // 0..15
    const int cc  = (tid & 15) * 16;         // byte offset in 256B row data
    const int gof = (tid & 15) * 8;          // halves

    auto issueKV = [&](int tile, int st) {
        const __half* kb = kb0 + (size_t)tile * 64 * INNER;
        const __half* vb = vb0 + (size_t)tile * 64 * INNER;
        uint32_t kd = ubs + KO * 2 + (uint32_t)st * KVSTG;
        uint32_t vd = ubs + VO * 2 + (uint32_t)st * KVSTG;
#pragma unroll
        for (int i = 0; i < 4; ++i) {
            int rr = rr0 + i * 16;
            cpa16(kd + rr * 272 + cc, kb + (size_t)rr * INNER + gof);
            cpa16(vd + rr * 272 + cc, vb + (size_t)rr * INNER + gof);
        }
    };

    issueKV(0, 0); CP_COMMIT();
    issueKV(1, 1); CP_COMMIT();

    // Load Q tile to smem, then hoist all Q fragments into registers.
#pragma unroll
    for (int it = 0; it < 8; ++it) {
        int idx = tid + it * 256;
        int r = idx >> 4;
        int c8 = (idx & 15) * 8;
        *(uint4*)(Qh + r * AQ_LD + c8) = *(const uint4*)(qb + (size_t)r * INNER + c8);
    }
    __syncthreads();

    const uint32_t uQ = ubs + (m0 + (lane & 15)) * (AQ_LD * 2) + (lane >> 4) * 16;
    uint32_t qf[8][4];
#pragma unroll
    for (int ks = 0; ks < 8; ++ks) ldmx4(qf[ks], uQ + ks * 32);

    const uint32_t uK = ubs + KO * 2 + (((lane >> 4) << 3) + (lane & 7)) * (AQ_LD * 2)
                        + ((lane >> 3) & 1) * 16;
    const uint32_t uV = ubs + VO * 2 + ((lane & 7) + ((lane >> 3) & 1) * 8) * (AQ_LD * 2)
                        + (lane >> 4) * 16;

    float m_[2] = {-INFINITY, -INFINITY};
    float l_[2] = {0.0f, 0.0f};
    float O[16][4];
#pragma unroll
    for (int nf = 0; nf < 16; ++nf)
#pragma unroll
        for (int r = 0; r < 4; ++r) O[nf][r] = 0.0f;

    int rd = 0;
    for (int kt = 0; kt < SEQ / 64; ++kt) {
        CP_WAIT1();                 // tile kt resident
        __syncthreads();
        {
            int ws = rd + 2; if (ws >= 3) ws -= 3;
            if (kt + 2 < SEQ / 64) issueKV(kt + 2, ws);
            CP_COMMIT();
        }

        const uint32_t uKs = uK + (uint32_t)rd * KVSTG;
        const uint32_t uVs = uV + (uint32_t)rd * KVSTG;

        // S = Q @ K^T
        float s[8][4];
#pragma unroll
        for (int nf = 0; nf < 8; ++nf)
#pragma unroll
            for (int r = 0; r < 4; ++r) s[nf][r] = 0.0f;

#pragma unroll
        for (int ks = 0; ks < 8; ++ks) {
#pragma unroll
            for (int w16 = 0; w16 < 4; ++w16) {
                uint32_t bk[4];
                ldmx4(bk, uKs + w16 * (16 * AQ_LD * 2) + ks * 32);
                mma_f16(s[2 * w16],     qf[ks], bk[0], bk[1]);
                mma_f16(s[2 * w16 + 1], qf[ks], bk[2], bk[3]);
            }
        }

        // Online softmax; P packed straight into PV A-fragments (registers).
        uint32_t pk[8][2];
#pragma unroll
        for (int i = 0; i < 2; ++i) {
            float mx = -INFINITY;
#pragma unroll
            for (int nf = 0; nf < 8; ++nf)
                mx = fmaxf(mx, fmaxf(s[nf][2 * i], s[nf][2 * i + 1]));
            mx = fmaxf(mx, __shfl_xor_sync(0xffffffffu, mx, 1));
            mx = fmaxf(mx, __shfl_xor_sync(0xffffffffu, mx, 2));
            float mn = fmaxf(m_[i], mx);
            float alpha = __expf(m_[i] - mn);
            float sum = 0.0f;
#pragma unroll
            for (int nf = 0; nf < 8; ++nf) {
                float p0 = __expf(s[nf][2 * i] - mn);
                float p1 = __expf(s[nf][2 * i + 1] - mn);
                sum += p0 + p1;
                __half2 ph = __floats2half2_rn(p0, p1);
                pk[nf][i] = *(uint32_t*)&ph;
            }
            sum += __shfl_xor_sync(0xffffffffu, sum, 1);
            sum += __shfl_xor_sync(0xffffffffu, sum, 2);
            l_[i] = l_[i] * alpha + sum;
            m_[i] = mn;
#pragma unroll
            for (int nf = 0; nf < 16; ++nf) {
                O[nf][2 * i]     *= alpha;
                O[nf][2 * i + 1] *= alpha;
            }
        }

        // O += P @ V   (A-fragments from pk registers; V via ldmatrix.trans)
#pragma unroll
        for (int ks = 0; ks < 4; ++ks) {
            uint32_t ap[4] = { pk[2 * ks][0], pk[2 * ks][1],
                               pk[2 * ks + 1][0], pk[2 * ks + 1][1] };
#pragma unroll
            for (int dp = 0; dp < 8; ++dp) {
                uint32_t bv[4];
                ldmx4t(bv, uVs + ks * (16 * AQ_LD * 2) + dp * 32);
                mma_f16(O[2 * dp],     ap, bv[0], bv[1]);
                mma_f16(O[2 * dp + 1], ap, bv[2], bv[3]);
            }
        }
        rd = (rd + 1 == 3) ? 0 : rd + 1;
    }

    // Epilogue: divide by l, store exact fp16 hi/lo split
#pragma unroll
    for (int i = 0; i < 2; ++i) {
        float inv = 1.0f / l_[i];
        int row = qt * 128 + m0 + g + 8 * i;
        size_t base = ((size_t)(b * SEQ + row)) * INNER + h * HDIM;
#pragma unroll
        for (int nf = 0; nf < 16; ++nf) {
            float v0 = O[nf][2 * i] * inv;
            float v1 = O[nf][2 * i + 1] * inv;
            __half h0 = __float2half_rn(v0);
            __half h1 = __float2half_rn(v1);
            __half e0 = __float2half_rn(v0 - __half2float(h0));
            __half e1 = __float2half_rn(v1 - __half2float(h1));
            *(__half2*)(oh + base + 8 * nf + 2 * tg) = __halves2half2(h0, h1);
            *(__half2*)(ol + base + 8 * nf + 2 * tg) = __halves2half2(e0, e1);
        }
    }
}

// ---------------------------------------------------------------------------
extern "C" void kernel_launch(void* const* d_in, const int* in_sizes, int n_in,
                              void* d_out, int out_size)
{
    const float* x    = (const float*)d_in[0];
    const float* rope = (const float*)d_in[1];
    const float* Wq   = (const float*)d_in[2];
    const float* Wk   = (const float*)d_in[3];
    const float* Wv   = (const float*)d_in[4];
    const float* Wo   = (const float*)d_in[5];
    const float* qnw  = (const float*)d_in[6];
    const float* knw  = (const float*)d_in[7];
    float* out = (float*)d_out;

    __half *xh, *xl, *wq, *wk, *wv, *wo, *qh, *kh, *vh, *oh, *ol;
    cudaGetSymbolAddress((void**)&xh, g_xh);
    cudaGetSymbolAddress((void**)&xl, g_xl);
    cudaGetSymbolAddress((void**)&wq, g_wq);
    cudaGetSymbolAddress((void**)&wk, g_wk);
    cudaGetSymbolAddress((void**)&wv, g_wv);
    cudaGetSymbolAddress((void**)&wo, g_wo);
    cudaGetSymbolAddress((void**)&qh, g_qh);
    cudaGetSymbolAddress((void**)&kh, g_kh);
    cudaGetSymbolAddress((void**)&vh, g_vh);
    cudaGetSymbolAddress((void**)&oh, g_oh);
    cudaGetSymbolAddress((void**)&ol, g_ol);

    cudaFuncSetAttribute(gemm_tc<0>, cudaFuncAttributeMaxDynamicSharedMemorySize, GEMM_SMEM);
    cudaFuncSetAttribute(gemm_tc<1>, cudaFuncAttributeMaxDynamicSharedMemorySize, GEMM_SMEM);
    cudaFuncSetAttribute(gemm_tc<2>, cudaFuncAttributeMaxDynamicSharedMemorySize, GEMM_SMEM);
    cudaFuncSetAttribute(gemm_tc<3>, cudaFuncAttributeMaxDynamicSharedMemorySize, GEMM_SMEM);
    cudaFuncSetAttribute(attn_kernel, cudaFuncAttributeMaxDynamicSharedMemorySize, (int)ATTN_SMEM);

    conv_split_x<<<(MROWS * DMODEL) / 1024, 256>>>(x, xh, xl);
    conv_w4<<<dim3((INNER * DMODEL) / 1024, 4), 256>>>(Wq, Wk, Wv, Wo, wq, wk, wv, wo);

    dim3 ggrid(INNER / 128, MROWS / 128);   // (16, 32)
    gemm_tc<3><<<ggrid, 256, GEMM_SMEM>>>(xh, xl, wq, qh, MROWS, INNER, DMODEL, qnw, rope);
    gemm_tc<2><<<ggrid, 256, GEMM_SMEM>>>(xh, xl, wk, kh, MROWS, INNER, DMODEL, knw, rope);
    gemm_tc<1><<<ggrid, 256, GEMM_SMEM>>>(xh, xl, wv, vh, MROWS, INNER, DMODEL, nullptr, nullptr);

    attn_kernel<<<dim3(SEQ / 128, NHEADS, BATCH), 256, ATTN_SMEM>>>(qh, kh, vh, oh, ol);

    dim3 ogrid(DMODEL / 128, MROWS / 128);
    gemm_tc<0><<<ogrid, 256, GEMM_SMEM>>>(oh, ol, wo, out, MROWS, DMODEL, INNER, nullptr, nullptr);
}

// round 17
// speedup vs baseline: 1.5308x; 1.5308x over previous
#include <cuda_runtime.h>
#include <cuda_fp16.h>
#include <math.h>
#include <stdint.h>

#define BATCH 2
#define SEQ   2048
#define DMODEL 2048
#define NHEADS 16
#define HDIM  128
#define INNER 2048   // NHEADS*HDIM
#define MROWS 4096   // BATCH*SEQ

// Scratch (device globals — allocation-free per harness rules)
__device__ __half g_xh[(size_t)MROWS * DMODEL];   // x hi fp16
__device__ __half g_xl[(size_t)MROWS * DMODEL];   // x lo fp16
__device__ __half g_wq[(size_t)INNER * DMODEL];
__device__ __half g_wk[(size_t)INNER * DMODEL];
__device__ __half g_wv[(size_t)INNER * DMODEL];
__device__ __half g_wo[(size_t)DMODEL * INNER];
__device__ __half g_qh[(size_t)MROWS * INNER];    // normed+roped+scaled Q
__device__ __half g_kh[(size_t)MROWS * INNER];    // normed+roped K
__device__ __half g_vh[(size_t)MROWS * INNER];    // V
__device__ __half g_oh[(size_t)MROWS * INNER];    // attn out hi
__device__ __half g_ol[(size_t)MROWS * INNER];    // attn out lo

// ===========================================================================
// helpers (sm_80-era features only — nothing 'a'-gated)
// ===========================================================================
__device__ __forceinline__ uint32_t smem_u32(const void* p) {
    uint32_t a;
    asm("{ .reg .u64 t; cvta.to.shared.u64 t, %1; cvt.u32.u64 %0, t; }"
        : "=r"(a) : "l"(p));
    return a;
}

__device__ __forceinline__ void mma_f16(float c[4], const uint32_t a[4],
                                        uint32_t b0, uint32_t b1) {
    asm volatile(
        "mma.sync.aligned.m16n8k16.row.col.f32.f16.f16.f32 "
        "{%0,%1,%2,%3}, {%4,%5,%6,%7}, {%8,%9}, {%0,%1,%2,%3};"
        : "+f"(c[0]), "+f"(c[1]), "+f"(c[2]), "+f"(c[3])
        : "r"(a[0]), "r"(a[1]), "r"(a[2]), "r"(a[3]), "r"(b0), "r"(b1));
}

__device__ __forceinline__ void ldmx4(uint32_t r[4], uint32_t addr) {
    asm volatile("ldmatrix.sync.aligned.m8n8.x4.shared.b16 {%0,%1,%2,%3}, [%4];"
                 : "=r"(r[0]), "=r"(r[1]), "=r"(r[2]), "=r"(r[3]) : "r"(addr));
}

__device__ __forceinline__ void ldmx4t(uint32_t r[4], uint32_t addr) {
    asm volatile("ldmatrix.sync.aligned.m8n8.x4.trans.shared.b16 {%0,%1,%2,%3}, [%4];"
                 : "=r"(r[0]), "=r"(r[1]), "=r"(r[2]), "=r"(r[3]) : "r"(addr));
}

__device__ __forceinline__ void cpa16(uint32_t s, const void* g) {
    asm volatile("cp.async.cg.shared.global [%0], [%1], 16;"
                 :: "r"(s), "l"(g) : "memory");
}
#define CP_COMMIT() asm volatile("cp.async.commit_group;" ::: "memory")
#define CP_WAIT1()  asm volatile("cp.async.wait_group 1;" ::: "memory")

__device__ __forceinline__ void split4(float4 v, __half2& h01, __half2& h23,
                                       __half2& l01, __half2& l23) {
    __half hx = __float2half_rn(v.x), hy = __float2half_rn(v.y);
    __half hz = __float2half_rn(v.z), hw = __float2half_rn(v.w);
    __half lx = __float2half_rn(v.x - __half2float(hx));
    __half ly = __float2half_rn(v.y - __half2float(hy));
    __half lz = __float2half_rn(v.z - __half2float(hz));
    __half lw = __float2half_rn(v.w - __half2float(hw));
    h01 = __halves2half2(hx, hy); h23 = __halves2half2(hz, hw);
    l01 = __halves2half2(lx, ly); l23 = __halves2half2(lz, lw);
}

// ===========================================================================
// Conversion kernels (run once; results reused across GEMMs)
// ===========================================================================
__global__ __launch_bounds__(256)
void conv_split_x(const float* __restrict__ in, __half* __restrict__ hi,
                  __half* __restrict__ lo)
{
    size_t i = ((size_t)blockIdx.x * 256 + threadIdx.x) * 4;
    float4 v = *(const float4*)(in + i);
    __half2 h01, h23, l01, l23;
    split4(v, h01, h23, l01, l23);
    *(__half2*)(hi + i)     = h01;
    *(__half2*)(hi + i + 2) = h23;
    *(__half2*)(lo + i)     = l01;
    *(__half2*)(lo + i + 2) = l23;
}

__global__ __launch_bounds__(256)
void conv_w4(const float* __restrict__ w0, const float* __restrict__ w1,
             const float* __restrict__ w2, const float* __restrict__ w3,
             __half* __restrict__ o0, __half* __restrict__ o1,
             __half* __restrict__ o2, __half* __restrict__ o3)
{
    int z = blockIdx.y;
    const float* src = (z == 0) ? w0 : (z == 1) ? w1 : (z == 2) ? w2 : w3;
    __half* dst      = (z == 0) ? o0 : (z == 1) ? o1 : (z == 2) ? o2 : o3;
    size_t i = ((size_t)blockIdx.x * 256 + threadIdx.x) * 4;
    float4 v = *(const float4*)(src + i);
    *(__half2*)(dst + i)     = __floats2half2_rn(v.x, v.y);
    *(__half2*)(dst + i + 2) = __floats2half2_rn(v.z, v.w);
}

// ===========================================================================
// GEMM: C[M,N] = (Ah+Al)[M,K] @ Bh[N,K]^T, all fp16 inputs in gmem.
// CTA tile 128x128, BK=32, 256 threads (warps 2Mx4N, 64x32),
// 3-stage cp.async pipeline, ldmatrix fragment loads.
// ===========================================================================
#define BM 128
#define BN 128
#define BK 32
#define LDH 40                              // halves per row (32 + 8 pad), 80 B
#define TILE_H (BM * LDH)                   // 5120 halves per tile
#define STG_H  (3 * TILE_H)                 // Ah, Al, Bh per stage
#define GEMM_SMEM (3 * STG_H * 2)           // 92160 bytes

template<int MODE>
__global__ __launch_bounds__(256, 2)
void gemm_tc(const __half* __restrict__ Ah, const __half* __restrict__ Al,
             const __half* __restrict__ Bh, void* __restrict__ Cout,
             int M, int N, int K,
             const float* __restrict__ w, const float* __restrict__ freqs)
{
    extern __shared__ __align__(16) __half smh[];

    const int tid  = threadIdx.x;
    const int lane = tid & 31;
    const int wid  = tid >> 5;
    const int wm   = (wid & 1) * 64;
    const int wn   = (wid >> 1) * 32;
    const int g    = lane >> 2;
    const int tg   = lane & 3;

    const int rowBase = blockIdx.y * BM;
    const int colBase = blockIdx.x * BN;

    const int cr = tid >> 2;             // 0..63
    const int c16 = tid & 3;             // chunk in 64B row
    const int gofs = c16 * 8;            // halves

    const uint32_t ub   = smem_u32(smh);
    const uint32_t aoff = (uint32_t)((wm + (lane & 15)) * (LDH * 2) + (lane >> 4) * 16);
    const uint32_t boff = (uint32_t)((wn + ((lane >> 4) << 3) + (lane & 7)) * (LDH * 2)
                                     + ((lane >> 3) & 1) * 16);

    float acc[4][4][4];
#pragma unroll
    for (int mi = 0; mi < 4; ++mi)
#pragma unroll
        for (int ni = 0; ni < 4; ++ni)
#pragma unroll
            for (int r = 0; r < 4; ++r) acc[mi][ni][r] = 0.0f;

    const int nkt = K / BK;

    auto issue = [&](int kt, int st) {
        const int k0 = kt * BK;
        uint32_t sb = ub + (uint32_t)st * (STG_H * 2);
        const __half* a0 = Ah + (size_t)(rowBase + cr) * K + k0 + gofs;
        const __half* a1 = Ah + (size_t)(rowBase + 64 + cr) * K + k0 + gofs;
        cpa16(sb + cr * 80 + c16 * 16, a0);
        cpa16(sb + (64 + cr) * 80 + c16 * 16, a1);
        const __half* l0 = Al + (size_t)(rowBase + cr) * K + k0 + gofs;
        const __half* l1 = Al + (size_t)(rowBase + 64 + cr) * K + k0 + gofs;
        cpa16(sb + TILE_H * 2 + cr * 80 + c16 * 16, l0);
        cpa16(sb + TILE_H * 2 + (64 + cr) * 80 + c16 * 16, l1);
        const __half* b0 = Bh + (size_t)(colBase + cr) * K + k0 + gofs;
        const __half* b1 = Bh + (size_t)(colBase + 64 + cr) * K + k0 + gofs;
        cpa16(sb + 2 * TILE_H * 2 + cr * 80 + c16 * 16, b0);
        cpa16(sb + 2 * TILE_H * 2 + (64 + cr) * 80 + c16 * 16, b1);
    };

    issue(0, 0); CP_COMMIT();
    issue(1, 1); CP_COMMIT();

    int rd = 0;
    for (int kt = 0; kt < nkt; ++kt) {
        CP_WAIT1();
        __syncthreads();
        {
            int ws = rd + 2; if (ws >= 3) ws -= 3;
            if (kt + 2 < nkt) issue(kt + 2, ws);
            CP_COMMIT();
        }

        const uint32_t sb = ub + (uint32_t)rd * (STG_H * 2);
        const uint32_t bAh = sb + aoff;
        const uint32_t bAl = sb + TILE_H * 2 + aoff;
        const uint32_t bBh = sb + 2 * TILE_H * 2 + boff;

#pragma unroll
        for (int ks = 0; ks < 2; ++ks) {
            uint32_t ah[4][4], al[4][4], bh[2][4];
#pragma unroll
            for (int mi = 0; mi < 4; ++mi)
                ldmx4(ah[mi], bAh + mi * (16 * LDH * 2) + ks * 32);
#pragma unroll
            for (int mi = 0; mi < 4; ++mi)
                ldmx4(al[mi], bAl + mi * (16 * LDH * 2) + ks * 32);
            ldmx4(bh[0], bBh + ks * 32);
            ldmx4(bh[1], bBh + 16 * LDH * 2 + ks * 32);
#pragma unroll
            for (int mi = 0; mi < 4; ++mi)
#pragma unroll
                for (int ni = 0; ni < 4; ++ni) {
                    uint32_t b0 = bh[ni >> 1][(ni & 1) * 2];
                    uint32_t b1 = bh[ni >> 1][(ni & 1) * 2 + 1];
                    mma_f16(acc[mi][ni], ah[mi], b0, b1);
                    mma_f16(acc[mi][ni], al[mi], b0, b1);
                }
        }
        rd = (rd + 1 == 3) ? 0 : rd + 1;
    }
    __syncthreads();

    // ---------------- Epilogue ----------------
    if (MODE == 0) {
        float* C = (float*)Cout;
#pragma unroll
        for (int mi = 0; mi < 4; ++mi) {
            const int r0 = rowBase + wm + mi * 16 + g;
#pragma unroll
            for (int ni = 0; ni < 4; ++ni) {
                const int c0 = colBase + wn + ni * 8 + tg * 2;
                *(float2*)(C + (size_t)r0 * N + c0) =
                    make_float2(acc[mi][ni][0], acc[mi][ni][1]);
                *(float2*)(C + (size_t)(r0 + 8) * N + c0) =
                    make_float2(acc[mi][ni][2], acc[mi][ni][3]);
            }
        }
    } else if (MODE == 1) {
        __half* C = (__half*)Cout;
#pragma unroll
        for (int mi = 0; mi < 4; ++mi) {
            const int r0 = rowBase + wm + mi * 16 + g;
#pragma unroll
            for (int ni = 0; ni < 4; ++ni) {
                const int c0 = colBase + wn + ni * 8 + tg * 2;
                *(__half2*)(C + (size_t)r0 * N + c0) =
                    __floats2half2_rn(acc[mi][ni][0], acc[mi][ni][1]);
                *(__half2*)(C + (size_t)(r0 + 8) * N + c0) =
                    __floats2half2_rn(acc[mi][ni][2], acc[mi][ni][3]);
            }
        }
    } else {
        float* red = (float*)smh;          // [128][4]
        float* stg = red + 512;            // [128][64]

#pragma unroll
        for (int mi = 0; mi < 4; ++mi) {
            float s0 = 0.0f, s1 = 0.0f;
#pragma unroll
            for (int ni = 0; ni < 4; ++ni) {
                s0 += acc[mi][ni][0] * acc[mi][ni][0] + acc[mi][ni][1] * acc[mi][ni][1];
                s1 += acc[mi][ni][2] * acc[mi][ni][2] + acc[mi][ni][3] * acc[mi][ni][3];
            }
            s0 += __shfl_xor_sync(0xffffffffu, s0, 1);
            s0 += __shfl_xor_sync(0xffffffffu, s0, 2);
            s1 += __shfl_xor_sync(0xffffffffu, s1, 1);
            s1 += __shfl_xor_sync(0xffffffffu, s1, 2);
            if (tg == 0) {
                red[(wm + mi * 16 + g) * 4 + (wn >> 5)]     = s0;
                red[(wm + mi * 16 + g + 8) * 4 + (wn >> 5)] = s1;
            }
        }
        __syncthreads();

        const float xsc = (MODE == 3) ? 0.08838834764831845f : 1.0f;
        float wc[4][2];
#pragma unroll
        for (int ni = 0; ni < 4; ++ni) {
            int c = wn + ni * 8 + tg * 2;
            wc[ni][0] = w[c]; wc[ni][1] = w[c + 1];
        }
#pragma unroll
        for (int mi = 0; mi < 4; ++mi) {
            int r = wm + mi * 16 + g;
            float4 p0 = *(float4*)&red[r * 4];
            float4 p1 = *(float4*)&red[(r + 8) * 4];
            float rms0 = rsqrtf((p0.x + p0.y + p0.z + p0.w) * (1.0f / 128.0f) + 1e-6f) * xsc;
            float rms1 = rsqrtf((p1.x + p1.y + p1.z + p1.w) * (1.0f / 128.0f) + 1e-6f) * xsc;
#pragma unroll
            for (int ni = 0; ni < 4; ++ni) {
                acc[mi][ni][0] *= rms0 * wc[ni][0];
                acc[mi][ni][1] *= rms0 * wc[ni][1];
                acc[mi][ni][2] *= rms1 * wc[ni][0];
                acc[mi][ni][3] *= rms1 * wc[ni][1];
            }
        }

        if (wn >= 64) {
#pragma unroll
            for (int mi = 0; mi < 4; ++mi) {
                int r = wm + mi * 16 + g;
#pragma unroll
                for (int ni = 0; ni < 4; ++ni) {
                    int cc = wn - 64 + ni * 8 + tg * 2;
                    *(float2*)&stg[r * 64 + cc] =
                        make_float2(acc[mi][ni][0], acc[mi][ni][1]);
                    *(float2*)&stg[(r + 8) * 64 + cc] =
                        make_float2(acc[mi][ni][2], acc[mi][ni][3]);
                }
            }
        }
        __syncthreads();

        if (wn < 64) {
            __half* C = (__half*)Cout;
#pragma unroll
            for (int mi = 0; mi < 4; ++mi) {
#pragma unroll
                for (int h2 = 0; h2 < 2; ++h2) {
                    int r = wm + mi * 16 + g + 8 * h2;
                    int rowg = rowBase + r;
                    int s = rowg & (SEQ - 1);
#pragma unroll
                    for (int ni = 0; ni < 4; ++ni) {
                        int j = wn + ni * 8 + tg * 2;
                        float nj0 = acc[mi][ni][2 * h2];
                        float nj1 = acc[mi][ni][2 * h2 + 1];
                        float2 mm = *(float2*)&stg[r * 64 + j];
                        float4 f0 = *(const float4*)(freqs + (size_t)s * 256 + j * 4);
                        float4 f1 = *(const float4*)(freqs + (size_t)s * 256 + (j + 1) * 4);
                        float oj0    = f0.x * nj0 + f0.y * mm.x;
                        float oj64_0 = f0.z * nj0 + f0.w * mm.x;
                        float oj1    = f1.x * nj1 + f1.y * mm.y;
                        float oj64_1 = f1.z * nj1 + f1.w * mm.y;
                        __half* cp = C + (size_t)rowg * N + colBase + j;
                        *(__half2*)cp        = __floats2half2_rn(oj0, oj1);
                        *(__half2*)(cp + 64) = __floats2half2_rn(oj64_0, oj64_1);
                    }
                }
            }
        }
    }
}

// ===========================================================================
// fp16 tensor flash attention. 256 threads (8 warps), BQ=128, BK=64, HDIM=128.
// 3-stage cp.async K/V pipeline. Q fragments preloaded to registers;
// P stays in registers (S accum layout == PV A-fragment layout).
// ===========================================================================
#define AQ_LD 136                            // 272 B rows, ldmatrix conflict-free
#define KO 17408                             // Q = 128*136 halves
#define VO (KO + 3 * 64 * AQ_LD)             // 43520
#define ATTN_SMEM ((VO + 3 * 64 * AQ_LD) * 2)   // 139264 bytes
#define KVSTG (64 * AQ_LD * 2)               // 17408 bytes per stage

__global__ __launch_bounds__(256)
void attn_kernel(const __half* __restrict__ q, const __half* __restrict__ k,
                 const __half* __restrict__ v,
                 __half* __restrict__ oh, __half* __restrict__ ol)
{
    extern __shared__ __align__(16) __half sh[];
    __half* Qh = sh;

    const int tid  = threadIdx.x;
    const int lane = tid & 31;
    const int wid  = tid >> 5;
    const int g    = lane >> 2;
    const int tg   = lane & 3;
    const int m0   = wid * 16;

    const int qt = blockIdx.x, h = blockIdx.y, b = blockIdx.z;
    const __half* qb  = q + ((size_t)(b * SEQ + qt * 128)) * INNER + h * HDIM;
    const __half* kb0 = k + (size_t)b * SEQ * INNER + h * HDIM;
    const __half* vb0 = v + (size_t)b * SEQ * INNER + h * HDIM;

    const uint32_t ubs = smem_u32(sh);
    const int rr0 = tid >> 4;                // 0..15
    const int cc  = (tid & 15) * 16;         // byte offset in 256B row data
    const int gof = (tid & 15) * 8;          // halves

    auto issueKV = [&](int tile, int st) {
        const __half* kb = kb0 + (size_t)tile * 64 * INNER;
        const __half* vb = vb0 + (size_t)tile * 64 * INNER;
        uint32_t kd = ubs + KO * 2 + (uint32_t)st * KVSTG;
        uint32_t vd = ubs + VO * 2 + (uint32_t)st * KVSTG;
#pragma unroll
        for (int i = 0; i < 4; ++i) {
            int rr = rr0 + i * 16;
            cpa16(kd + rr * 272 + cc, kb + (size_t)rr * INNER + gof);
            cpa16(vd + rr * 272 + cc, vb + (size_t)rr * INNER + gof);
        }
    };

    issueKV(0, 0); CP_COMMIT();
    issueKV(1, 1); CP_COMMIT();

    // Load Q tile to smem, then hoist all Q fragments into registers.
#pragma unroll
    for (int it = 0; it < 8; ++it) {
        int idx = tid + it * 256;
        int r = idx >> 4;
        int c8 = (idx & 15) * 8;
        *(uint4*)(Qh + r * AQ_LD + c8) = *(const uint4*)(qb + (size_t)r * INNER + c8);
    }
    __syncthreads();

    const uint32_t uQ = ubs + (m0 + (lane & 15)) * (AQ_LD * 2) + (lane >> 4) * 16;
    uint32_t qf[8][4];
#pragma unroll
    for (int ks = 0; ks < 8; ++ks) ldmx4(qf[ks], uQ + ks * 32);

    const uint32_t uK = ubs + KO * 2 + (((lane >> 4) << 3) + (lane & 7)) * (AQ_LD * 2)
                        + ((lane >> 3) & 1) * 16;
    const uint32_t uV = ubs + VO * 2 + ((lane & 7) + ((lane >> 3) & 1) * 8) * (AQ_LD * 2)
                        + (lane >> 4) * 16;

    float m_[2] = {-INFINITY, -INFINITY};
    float l_[2] = {0.0f, 0.0f};
    float O[16][4];
#pragma unroll
    for (int nf = 0; nf < 16; ++nf)
#pragma unroll
        for (int r = 0; r < 4; ++r) O[nf][r] = 0.0f;

    int rd = 0;
    for (int kt = 0; kt < SEQ / 64; ++kt) {
        CP_WAIT1();                 // tile kt resident
        __syncthreads();
        {
            int ws = rd + 2; if (ws >= 3) ws -= 3;
            if (kt + 2 < SEQ / 64) issueKV(kt + 2, ws);
            CP_COMMIT();
        }

        const uint32_t uKs = uK + (uint32_t)rd * KVSTG;
        const uint32_t uVs = uV + (uint32_t)rd * KVSTG;

        // S = Q @ K^T
        float s[8][4];
#pragma unroll
        for (int nf = 0; nf < 8; ++nf)
#pragma unroll
            for (int r = 0; r < 4; ++r) s[nf][r] = 0.0f;

#pragma unroll
        for (int ks = 0; ks < 8; ++ks) {
#pragma unroll
            for (int w16 = 0; w16 < 4; ++w16) {
                uint32_t bk[4];
                ldmx4(bk, uKs + w16 * (16 * AQ_LD * 2) + ks * 32);
                mma_f16(s[2 * w16],     qf[ks], bk[0], bk[1]);
                mma_f16(s[2 * w16 + 1], qf[ks], bk[2], bk[3]);
            }
        }

        // Online softmax; P packed straight into PV A-fragments (registers).
        uint32_t pk[8][2];
#pragma unroll
        for (int i = 0; i < 2; ++i) {
            float mx = -INFINITY;
#pragma unroll
            for (int nf = 0; nf < 8; ++nf)
                mx = fmaxf(mx, fmaxf(s[nf][2 * i], s[nf][2 * i + 1]));
            mx = fmaxf(mx, __shfl_xor_sync(0xffffffffu, mx, 1));
            mx = fmaxf(mx, __shfl_xor_sync(0xffffffffu, mx, 2));
            float mn = fmaxf(m_[i], mx);
            float alpha = __expf(m_[i] - mn);
            float sum = 0.0f;
#pragma unroll
            for (int nf = 0; nf < 8; ++nf) {
                float p0 = __expf(s[nf][2 * i] - mn);
                float p1 = __expf(s[nf][2 * i + 1] - mn);
                sum += p0 + p1;
                __half2 ph = __floats2half2_rn(p0, p1);
                pk[nf][i] = *(uint32_t*)&ph;
            }
            sum += __shfl_xor_sync(0xffffffffu, sum, 1);
            sum += __shfl_xor_sync(0xffffffffu, sum, 2);
            l_[i] = l_[i] * alpha + sum;
            m_[i] = mn;
#pragma unroll
            for (int nf = 0; nf < 16; ++nf) {
                O[nf][2 * i]     *= alpha;
                O[nf][2 * i + 1] *= alpha;
            }
        }

        // O += P @ V   (A-fragments from pk registers; V via ldmatrix.trans)
#pragma unroll
        for (int ks = 0; ks < 4; ++ks) {
            uint32_t ap[4] = { pk[2 * ks][0], pk[2 * ks][1],
                               pk[2 * ks + 1][0], pk[2 * ks + 1][1] };
#pragma unroll
            for (int dp = 0; dp < 8; ++dp) {
                uint32_t bv[4];
                ldmx4t(bv, uVs + ks * (16 * AQ_LD * 2) + dp * 32);
                mma_f16(O[2 * dp],     ap, bv[0], bv[1]);
                mma_f16(O[2 * dp + 1], ap, bv[2], bv[3]);
            }
        }
        rd = (rd + 1 == 3) ? 0 : rd + 1;
    }

    // Epilogue: divide by l, store exact fp16 hi/lo split
#pragma unroll
    for (int i = 0; i < 2; ++i) {
        float inv = 1.0f / l_[i];
        int row = qt * 128 + m0 + g + 8 * i;
        size_t base = ((size_t)(b * SEQ + row)) * INNER + h * HDIM;
#pragma unroll
        for (int nf = 0; nf < 16; ++nf) {
            float v0 = O[nf][2 * i] * inv;
            float v1 = O[nf][2 * i + 1] * inv;
            __half h0 = __float2half_rn(v0);
            __half h1 = __float2half_rn(v1);
            __half e0 = __float2half_rn(v0 - __half2float(h0));
            __half e1 = __float2half_rn(v1 - __half2float(h1));
            *(__half2*)(oh + base + 8 * nf + 2 * tg) = __halves2half2(h0, h1);
            *(__half2*)(ol + base + 8 * nf + 2 * tg) = __halves2half2(e0, e1);
        }
    }
}

// ---------------------------------------------------------------------------
extern "C" void kernel_launch(void* const* d_in, const int* in_sizes, int n_in,
                              void* d_out, int out_size)
{
    const float* x    = (const float*)d_in[0];
    const float* rope = (const float*)d_in[1];
    const float* Wq   = (const float*)d_in[2];
    const float* Wk   = (const float*)d_in[3];
    const float* Wv   = (const float*)d_in[4];
    const float* Wo   = (const float*)d_in[5];
    const float* qnw  = (const float*)d_in[6];
    const float* knw  = (const float*)d_in[7];
    float* out = (float*)d_out;

    __half *xh, *xl, *wq, *wk, *wv, *wo, *qh, *kh, *vh, *oh, *ol;
    cudaGetSymbolAddress((void**)&xh, g_xh);
    cudaGetSymbolAddress((void**)&xl, g_xl);
    cudaGetSymbolAddress((void**)&wq, g_wq);
    cudaGetSymbolAddress((void**)&wk, g_wk);
    cudaGetSymbolAddress((void**)&wv, g_wv);
    cudaGetSymbolAddress((void**)&wo, g_wo);
    cudaGetSymbolAddress((void**)&qh, g_qh);
    cudaGetSymbolAddress((void**)&kh, g_kh);
    cudaGetSymbolAddress((void**)&vh, g_vh);
    cudaGetSymbolAddress((void**)&oh, g_oh);
    cudaGetSymbolAddress((void**)&ol, g_ol);

    cudaFuncSetAttribute(gemm_tc<0>, cudaFuncAttributeMaxDynamicSharedMemorySize, GEMM_SMEM);
    cudaFuncSetAttribute(gemm_tc<1>, cudaFuncAttributeMaxDynamicSharedMemorySize, GEMM_SMEM);
    cudaFuncSetAttribute(gemm_tc<2>, cudaFuncAttributeMaxDynamicSharedMemorySize, GEMM_SMEM);
    cudaFuncSetAttribute(gemm_tc<3>, cudaFuncAttributeMaxDynamicSharedMemorySize, GEMM_SMEM);
    cudaFuncSetAttribute(attn_kernel, cudaFuncAttributeMaxDynamicSharedMemorySize, (int)ATTN_SMEM);

    conv_split_x<<<(MROWS * DMODEL) / 1024, 256>>>(x, xh, xl);
    conv_w4<<<dim3((INNER * DMODEL) / 1024, 4), 256>>>(Wq, Wk, Wv, Wo, wq, wk, wv, wo);

    dim3 ggrid(INNER / 128, MROWS / 128);   // (16, 32)
    gemm_tc<3><<<ggrid, 256, GEMM_SMEM>>>(xh, xl, wq, qh, MROWS, INNER, DMODEL, qnw, rope);
    gemm_tc<2><<<ggrid, 256, GEMM_SMEM>>>(xh, xl, wk, kh, MROWS, INNER, DMODEL, knw, rope);
    gemm_tc<1><<<ggrid, 256, GEMM_SMEM>>>(xh, xl, wv, vh, MROWS, INNER, DMODEL, nullptr, nullptr);

    attn_kernel<<<dim3(SEQ / 128, NHEADS, BATCH), 256, ATTN_SMEM>>>(qh, kh, vh, oh, ol);

    dim3 ogrid(DMODEL / 128, MROWS / 128);
    gemm_tc<0><<<ogrid, 256, GEMM_SMEM>>>(oh, ol, wo, out, MROWS, DMODEL, INNER, nullptr, nullptr);
}